// round 14
// baseline (speedup 1.0000x reference)
#include <cuda_runtime.h>

// ---------------- problem constants ----------------
#define NV 2000000
#define NF 4000000
#define NITERS 10

__device__ __forceinline__ float k_DT()   { return 1e-8f; }
__device__ __forceinline__ float k_ST()   { return 1.0f; }
__device__ __forceinline__ float k_BULK() { return 2500.0f; }
__device__ __forceinline__ float k_EPS()  { return 1e-12f; }
// TARGET_CELL_VOLUME * exp(100/2500) in fp32
__device__ __forceinline__ float k_VTGT() { return 1.0408107741923882f; }

// ---------------- device scratch (no allocations allowed) ----------------
__device__ int    g_fidx[(size_t)NF * 3];   // 48 MB int32 face indices (clamped)
__device__ float  g_facc[(size_t)NV * 3];   // 24 MB force accumulator
__device__ double g_vol;                    // 6*volume accumulator
__device__ int    g_is64;                   // 1 if faces buffer is int64, else 0

// ---------------- small vector helpers ----------------
struct f3 { float x, y, z; };

__device__ __forceinline__ f3 f3sub(f3 a, f3 b) { return {a.x - b.x, a.y - b.y, a.z - b.z}; }
__device__ __forceinline__ f3 f3cross(f3 a, f3 b) {
    return {a.y * b.z - a.z * b.y,
            a.z * b.x - a.x * b.z,
            a.x * b.y - a.y * b.x};
}
__device__ __forceinline__ float f3dot(f3 a, f3 b) { return a.x * b.x + a.y * b.y + a.z * b.z; }

__device__ __forceinline__ f3 load_vert(const float* __restrict__ x, int i) {
    int b = 3 * i;
    return { __ldg(x + b), __ldg(x + b + 1), __ldg(x + b + 2) };
}

__device__ __forceinline__ void scatter_add(int i, f3 v) {
    int b = 3 * i;
    atomicAdd(&g_facc[b],     v.x);
    atomicAdd(&g_facc[b + 1], v.y);
    atomicAdd(&g_facc[b + 2], v.z);
}

// ---------------- kernels ----------------

// Detect whether the faces buffer holds int64 or int32 indices.
// Reads only within the first NF*3 int32 words (safe for both widths).
// For int64 (little-endian, values in [0, 2e6)), every odd 4-byte word is 0.
__global__ void k_detect(const int* __restrict__ raw) {
    __shared__ int s_or;
    if (threadIdx.x == 0) s_or = 0;
    __syncthreads();
    int acc = 0;
    // 256 threads * 16 samples = 4096 odd-word probes spread over first 12M ints
    for (int j = 0; j < 16; ++j) {
        int k = threadIdx.x * 16 + j;                 // 0..4095
        int pos = 1 + 2 * (k * 1464);                 // odd positions, < 12M
        acc |= raw[pos];
    }
    atomicOr(&s_or, acc);
    __syncthreads();
    if (threadIdx.x == 0) g_is64 = (s_or == 0) ? 1 : 0;
}

// Convert faces (either width) -> clamped int32 indices. Scalar loads only.
__global__ void k_convert(const int* __restrict__ raw) {
    int n = NF * 3;
    int stride = gridDim.x * blockDim.x;
    bool is64 = (g_is64 != 0);
    for (int i = blockIdx.x * blockDim.x + threadIdx.x; i < n; i += stride) {
        int v = is64 ? raw[2 * i] : raw[i];           // low word if int64 (LE)
        unsigned uv = (unsigned)v;
        if (uv >= (unsigned)NV) uv = NV - 1;          // clamp: no downstream trap possible
        g_fidx[i] = (int)uv;
    }
}

// zero force accumulator + volume
__global__ void k_zero() {
    int stride = gridDim.x * blockDim.x;
    for (int i = blockIdx.x * blockDim.x + threadIdx.x; i < NV * 3; i += stride)
        g_facc[i] = 0.0f;
    if (blockIdx.x == 0 && threadIdx.x == 0) g_vol = 0.0;
}

// pass A: accumulate 6*volume = sum_f dot(v0, cross(v1,v2))
__global__ void __launch_bounds__(256) k_vol(const float* __restrict__ x) {
    float s = 0.f;
    int stride = gridDim.x * blockDim.x;
    for (int f = blockIdx.x * blockDim.x + threadIdx.x; f < NF; f += stride) {
        int b = 3 * f;
        int i0 = __ldcs(g_fidx + b);
        int i1 = __ldcs(g_fidx + b + 1);
        int i2 = __ldcs(g_fidx + b + 2);
        f3 v0 = load_vert(x, i0);
        f3 v1 = load_vert(x, i1);
        f3 v2 = load_vert(x, i2);
        s += f3dot(v0, f3cross(v1, v2));
    }
    #pragma unroll
    for (int o = 16; o; o >>= 1) s += __shfl_xor_sync(0xffffffffu, s, o);
    __shared__ float ws[8];
    int w = threadIdx.x >> 5, lane = threadIdx.x & 31;
    if (lane == 0) ws[w] = s;
    __syncthreads();
    if (threadIdx.x == 0) {
        float t = 0.f;
        #pragma unroll
        for (int j = 0; j < 8; j++) t += ws[j];
        atomicAdd(&g_vol, (double)t);
    }
}

// pass B: per-face forces with p known, scalar atomic scatter
__global__ void __launch_bounds__(256) k_force(const float* __restrict__ x) {
    int f = blockIdx.x * blockDim.x + threadIdx.x;
    if (f >= NF) return;

    float vol = (float)g_vol * (1.0f / 6.0f);
    float p   = k_BULK() * (k_VTGT() - vol) / k_VTGT();
    float k6  = p * (1.0f / 6.0f);
    float hA  = -0.5f * k_ST();

    int b = 3 * f;
    int i0 = __ldcs(g_fidx + b);
    int i1 = __ldcs(g_fidx + b + 1);
    int i2 = __ldcs(g_fidx + b + 2);

    f3 v0 = load_vert(x, i0);
    f3 v1 = load_vert(x, i1);
    f3 v2 = load_vert(x, i2);

    f3 e1 = f3sub(v1, v0);
    f3 e2 = f3sub(v2, v0);
    f3 n  = f3cross(e1, e2);
    float nn  = sqrtf(f3dot(n, n));
    float inv = 1.0f / (nn + k_EPS());
    f3 nh = { n.x * inv, n.y * inv, n.z * inv };

    f3 dA0 = f3cross(nh, f3sub(v2, v1));
    f3 dA1 = f3cross(nh, f3sub(v0, v2));
    f3 dA2 = f3cross(nh, e1);

    f3 c12 = f3cross(v1, v2);
    f3 c20 = f3cross(v2, v0);
    f3 c01 = f3cross(v0, v1);

    f3 f0 = { hA * dA0.x + k6 * c12.x, hA * dA0.y + k6 * c12.y, hA * dA0.z + k6 * c12.z };
    f3 f1 = { hA * dA1.x + k6 * c20.x, hA * dA1.y + k6 * c20.y, hA * dA1.z + k6 * c20.z };
    f3 f2 = { hA * dA2.x + k6 * c01.x, hA * dA2.y + k6 * c01.y, hA * dA2.z + k6 * c01.z };

    scatter_add(i0, f0);
    scatter_add(i1, f1);
    scatter_add(i2, f2);
}

// pass C: x += dt*F; re-zero accumulator + volume for next iteration
__global__ void k_update(float* __restrict__ x) {
    int stride = gridDim.x * blockDim.x;
    for (int i = blockIdx.x * blockDim.x + threadIdx.x; i < NV * 3; i += stride) {
        x[i] += k_DT() * g_facc[i];
        g_facc[i] = 0.0f;
    }
    if (blockIdx.x == 0 && threadIdx.x == 0) g_vol = 0.0;
}

// ---------------- launch ----------------
extern "C" void kernel_launch(void* const* d_in, const int* in_sizes, int n_in,
                              void* d_out, int out_size) {
    // Identify inputs by size; accept element counts OR byte counts for
    // either faces dtype. Fall back to positional order.
    const float* verts = nullptr;
    const void*  faces = nullptr;
    for (int i = 0; i < n_in; ++i) {
        long long s = in_sizes[i];
        if (s == 6000000LL || s == 24000000LL) {
            verts = (const float*)d_in[i];
        } else if (s == 12000000LL || s == 48000000LL || s == 96000000LL) {
            faces = (const void*)d_in[i];
        }
    }
    if (!verts && n_in > 0) verts = (const float*)d_in[0];
    if (!faces && n_in > 1) faces = (const void*)d_in[1];

    float* x = (float*)d_out;   // working positions, 6M floats
    (void)out_size;

    // x <- initial vertices
    cudaMemcpyAsync(x, verts, (size_t)NV * 3 * sizeof(float), cudaMemcpyDeviceToDevice);

    // detect faces width, then convert -> clamped int32
    k_detect<<<1, 256>>>((const int*)faces);
    k_convert<<<8192, 256>>>((const int*)faces);

    // zero accumulators
    k_zero<<<4096, 256>>>();

    const int FB = (NF + 255) / 256;
    for (int it = 0; it < NITERS; ++it) {
        k_vol<<<4096, 256>>>(x);
        k_force<<<FB, 256>>>(x);
        k_update<<<4096, 256>>>(x);
    }
}

// round 17
// speedup vs baseline: 1.0008x; 1.0008x over previous
#include <cuda_runtime.h>

// ---------------- problem constants ----------------
#define NV 2000000
#define NF 4000000
#define NITERS 10

__device__ __forceinline__ float k_DT()   { return 1e-8f; }
__device__ __forceinline__ float k_ST()   { return 1.0f; }
__device__ __forceinline__ float k_BULK() { return 2500.0f; }
__device__ __forceinline__ float k_EPS()  { return 1e-12f; }
// TARGET_CELL_VOLUME * exp(100/2500) in fp32
__device__ __forceinline__ float k_VTGT() { return 1.0408107741923882f; }

// ---------------- device scratch (no allocations allowed) ----------------
__device__ int    g_fidx[(size_t)NF * 3];   // 48 MB int32 face indices (clamped)
__device__ float  g_facc[(size_t)NV * 3];   // 24 MB force accumulator
__device__ double g_vol;                    // 6*volume accumulator
__device__ int    g_is64;                   // 1 if faces buffer is int64, else 0

// ---------------- small vector helpers ----------------
struct f3 { float x, y, z; };

__device__ __forceinline__ f3 f3sub(f3 a, f3 b) { return {a.x - b.x, a.y - b.y, a.z - b.z}; }
__device__ __forceinline__ f3 f3cross(f3 a, f3 b) {
    return {a.y * b.z - a.z * b.y,
            a.z * b.x - a.x * b.z,
            a.x * b.y - a.y * b.x};
}
__device__ __forceinline__ float f3dot(f3 a, f3 b) { return a.x * b.x + a.y * b.y + a.z * b.z; }

__device__ __forceinline__ f3 load_vert(const float* __restrict__ x, int i) {
    int b = 3 * i;
    return { __ldg(x + b), __ldg(x + b + 1), __ldg(x + b + 2) };
}

__device__ __forceinline__ void scatter_add(int i, f3 v) {
    int b = 3 * i;
    atomicAdd(&g_facc[b],     v.x);
    atomicAdd(&g_facc[b + 1], v.y);
    atomicAdd(&g_facc[b + 2], v.z);
}

// ---------------- kernels ----------------

// Detect whether the faces buffer holds int64 or int32 indices.
// Reads only within the first NF*3 int32 words (safe for both widths).
// For int64 (little-endian, values in [0, 2e6)), every odd 4-byte word is 0.
__global__ void k_detect(const int* __restrict__ raw) {
    __shared__ int s_or;
    if (threadIdx.x == 0) s_or = 0;
    __syncthreads();
    int acc = 0;
    // 256 threads * 16 samples = 4096 odd-word probes spread over first 12M ints
    for (int j = 0; j < 16; ++j) {
        int k = threadIdx.x * 16 + j;                 // 0..4095
        int pos = 1 + 2 * (k * 1464);                 // odd positions, < 12M
        acc |= raw[pos];
    }
    atomicOr(&s_or, acc);
    __syncthreads();
    if (threadIdx.x == 0) g_is64 = (s_or == 0) ? 1 : 0;
}

// Convert faces (either width) -> clamped int32 indices. Scalar loads only.
__global__ void k_convert(const int* __restrict__ raw) {
    int n = NF * 3;
    int stride = gridDim.x * blockDim.x;
    bool is64 = (g_is64 != 0);
    for (int i = blockIdx.x * blockDim.x + threadIdx.x; i < n; i += stride) {
        int v = is64 ? raw[2 * i] : raw[i];           // low word if int64 (LE)
        unsigned uv = (unsigned)v;
        if (uv >= (unsigned)NV) uv = NV - 1;          // clamp: no downstream trap possible
        g_fidx[i] = (int)uv;
    }
}

// zero force accumulator + volume
__global__ void k_zero() {
    int stride = gridDim.x * blockDim.x;
    for (int i = blockIdx.x * blockDim.x + threadIdx.x; i < NV * 3; i += stride)
        g_facc[i] = 0.0f;
    if (blockIdx.x == 0 && threadIdx.x == 0) g_vol = 0.0;
}

// pass A: accumulate 6*volume = sum_f dot(v0, cross(v1,v2))
__global__ void __launch_bounds__(256) k_vol(const float* __restrict__ x) {
    float s = 0.f;
    int stride = gridDim.x * blockDim.x;
    for (int f = blockIdx.x * blockDim.x + threadIdx.x; f < NF; f += stride) {
        int b = 3 * f;
        int i0 = __ldcs(g_fidx + b);
        int i1 = __ldcs(g_fidx + b + 1);
        int i2 = __ldcs(g_fidx + b + 2);
        f3 v0 = load_vert(x, i0);
        f3 v1 = load_vert(x, i1);
        f3 v2 = load_vert(x, i2);
        s += f3dot(v0, f3cross(v1, v2));
    }
    #pragma unroll
    for (int o = 16; o; o >>= 1) s += __shfl_xor_sync(0xffffffffu, s, o);
    __shared__ float ws[8];
    int w = threadIdx.x >> 5, lane = threadIdx.x & 31;
    if (lane == 0) ws[w] = s;
    __syncthreads();
    if (threadIdx.x == 0) {
        float t = 0.f;
        #pragma unroll
        for (int j = 0; j < 8; j++) t += ws[j];
        atomicAdd(&g_vol, (double)t);
    }
}

// pass B: per-face forces with p known, scalar atomic scatter
__global__ void __launch_bounds__(256) k_force(const float* __restrict__ x) {
    int f = blockIdx.x * blockDim.x + threadIdx.x;
    if (f >= NF) return;

    float vol = (float)g_vol * (1.0f / 6.0f);
    float p   = k_BULK() * (k_VTGT() - vol) / k_VTGT();
    float k6  = p * (1.0f / 6.0f);
    float hA  = -0.5f * k_ST();

    int b = 3 * f;
    int i0 = __ldcs(g_fidx + b);
    int i1 = __ldcs(g_fidx + b + 1);
    int i2 = __ldcs(g_fidx + b + 2);

    f3 v0 = load_vert(x, i0);
    f3 v1 = load_vert(x, i1);
    f3 v2 = load_vert(x, i2);

    f3 e1 = f3sub(v1, v0);
    f3 e2 = f3sub(v2, v0);
    f3 n  = f3cross(e1, e2);
    float nn  = sqrtf(f3dot(n, n));
    float inv = 1.0f / (nn + k_EPS());
    f3 nh = { n.x * inv, n.y * inv, n.z * inv };

    f3 dA0 = f3cross(nh, f3sub(v2, v1));
    f3 dA1 = f3cross(nh, f3sub(v0, v2));
    f3 dA2 = f3cross(nh, e1);

    f3 c12 = f3cross(v1, v2);
    f3 c20 = f3cross(v2, v0);
    f3 c01 = f3cross(v0, v1);

    f3 f0 = { hA * dA0.x + k6 * c12.x, hA * dA0.y + k6 * c12.y, hA * dA0.z + k6 * c12.z };
    f3 f1 = { hA * dA1.x + k6 * c20.x, hA * dA1.y + k6 * c20.y, hA * dA1.z + k6 * c20.z };
    f3 f2 = { hA * dA2.x + k6 * c01.x, hA * dA2.y + k6 * c01.y, hA * dA2.z + k6 * c01.z };

    scatter_add(i0, f0);
    scatter_add(i1, f1);
    scatter_add(i2, f2);
}

// pass C: x += dt*F; re-zero accumulator + volume for next iteration
__global__ void k_update(float* __restrict__ x) {
    int stride = gridDim.x * blockDim.x;
    for (int i = blockIdx.x * blockDim.x + threadIdx.x; i < NV * 3; i += stride) {
        x[i] += k_DT() * g_facc[i];
        g_facc[i] = 0.0f;
    }
    if (blockIdx.x == 0 && threadIdx.x == 0) g_vol = 0.0;
}

// ---------------- launch ----------------
extern "C" void kernel_launch(void* const* d_in, const int* in_sizes, int n_in,
                              void* d_out, int out_size) {
    // Identify inputs by size; accept element counts OR byte counts for
    // either faces dtype. Fall back to positional order.
    const float* verts = nullptr;
    const void*  faces = nullptr;
    for (int i = 0; i < n_in; ++i) {
        long long s = in_sizes[i];
        if (s == 6000000LL || s == 24000000LL) {
            verts = (const float*)d_in[i];
        } else if (s == 12000000LL || s == 48000000LL || s == 96000000LL) {
            faces = (const void*)d_in[i];
        }
    }
    if (!verts && n_in > 0) verts = (const float*)d_in[0];
    if (!faces && n_in > 1) faces = (const void*)d_in[1];

    float* x = (float*)d_out;   // working positions, 6M floats
    (void)out_size;

    // x <- initial vertices
    cudaMemcpyAsync(x, verts, (size_t)NV * 3 * sizeof(float), cudaMemcpyDeviceToDevice);

    // detect faces width, then convert -> clamped int32
    k_detect<<<1, 256>>>((const int*)faces);
    k_convert<<<8192, 256>>>((const int*)faces);

    // zero accumulators
    k_zero<<<4096, 256>>>();

    const int FB = (NF + 255) / 256;
    for (int it = 0; it < NITERS; ++it) {
        k_vol<<<4096, 256>>>(x);
        k_force<<<FB, 256>>>(x);
        k_update<<<4096, 256>>>(x);
    }
}